// round 1
// baseline (speedup 1.0000x reference)
#include <cuda_runtime.h>
#include <cstdint>
#include <cstddef>

// Problem constants
constexpr int Nn = 100000;   // nodes
constexpr int Ee = 500000;   // edges per relation
constexpr int Rr = 3;        // relations
constexpr int Ll = 2;        // layers
constexpr int Ff = 300;      // input features
constexpr int Hh = 256;      // hidden
constexpr int Cc = 23;       // classes

// -------- device scratch (static globals: no runtime allocation) --------
__device__ float g_h[(size_t)Nn * Hh];            // current node features
__device__ float g_acc[(size_t)Nn * Hh];          // pre-BN accumulator
__device__ float g_m[(size_t)Nn * 3 * Hh];        // scattered messages [N, 3H]
__device__ float g_coef[Rr * Ee];                 // per-edge coefficient
__device__ int   g_dout[Rr * Nn];
__device__ int   g_din[Rr * Nn];
__device__ float g_bias[Hh];                      // combined skip+mean(gcn) bias
__device__ float g_sum[Hh];
__device__ float g_sq[Hh];
__device__ float g_scale[Hh];
__device__ float g_shift[Hh];

// ---------------------------------------------------------------
// Generic zero (float4 granularity, grid-stride)
__global__ void zero_k(float4* __restrict__ p, int n4) {
    int i = blockIdx.x * blockDim.x + threadIdx.x;
    int stride = gridDim.x * blockDim.x;
    float4 z = make_float4(0.f, 0.f, 0.f, 0.f);
    for (; i < n4; i += stride) p[i] = z;
}

// Degree counting over all relations' edges
__global__ void deg_k(const int* __restrict__ src, const int* __restrict__ dst,
                      int* __restrict__ doutA, int* __restrict__ dinA) {
    int i = blockIdx.x * blockDim.x + threadIdx.x;
    if (i >= Rr * Ee) return;
    int r = i / Ee;
    atomicAdd(&doutA[r * Nn + src[i]], 1);
    atomicAdd(&dinA[r * Nn + dst[i]], 1);
}

// Per-edge coefficient: rsqrt(clip(dout,1)) * rsqrt(clip(din,1)) / 3
__global__ void coef_k(const int* __restrict__ src, const int* __restrict__ dst,
                       const int* __restrict__ doutA, const int* __restrict__ dinA,
                       float* __restrict__ coef) {
    int i = blockIdx.x * blockDim.x + threadIdx.x;
    if (i >= Rr * Ee) return;
    int r = i / Ee;
    float o = (float)max(doutA[r * Nn + src[i]], 1);
    float d = (float)max(dinA[r * Nn + dst[i]], 1);
    coef[i] = rsqrtf(o) * rsqrtf(d) * (1.f / 3.f);
}

// Scatter: one warp per edge. m[dst, r*H : (r+1)*H] += coef * h[src, :]
// Uses sm_90+ vectorized reductions (red.global.add.v4.f32).
__global__ void scatter_k(const float* __restrict__ h,
                          const int* __restrict__ src, const int* __restrict__ dst,
                          const float* __restrict__ coef, float* __restrict__ m) {
    int gw = (blockIdx.x * blockDim.x + threadIdx.x) >> 5;
    int lane = threadIdx.x & 31;
    if (gw >= Rr * Ee) return;
    int r = gw / Ee;
    int s = __ldg(&src[gw]);
    int d = __ldg(&dst[gw]);
    float c = __ldg(&coef[gw]);
    const float4* hs = (const float4*)(h + (size_t)s * Hh);
    float4* md = (float4*)(m + (size_t)d * (3 * Hh) + r * Hh);
#pragma unroll
    for (int t = 0; t < 2; t++) {
        float4 v = hs[lane + t * 32];
        float4 w = make_float4(v.x * c, v.y * c, v.z * c, v.w * c);
        asm volatile("red.global.add.v4.f32 [%0], {%1,%2,%3,%4};"
                     :: "l"(md + lane + t * 32),
                        "f"(w.x), "f"(w.y), "f"(w.z), "f"(w.w)
                     : "memory");
    }
}

// Combined bias for a layer: skip_b + mean_r gcn_b
__global__ void bias_k(const float* __restrict__ skip_b,
                       const float* __restrict__ gcn_b,
                       float* __restrict__ bias) {
    int t = threadIdx.x;
    bias[t] = skip_b[t] + (gcn_b[t] + gcn_b[Hh + t] + gcn_b[2 * Hh + t]) * (1.f / 3.f);
}

// ---------------------------------------------------------------
// Tiled fp32 GEMM: C[M,Nc] (+)= A[M,K] @ B[K,Nc] (+ bias).
// BM=128, BN=64, BK=16, 256 threads, 8x4 per thread.
template <bool ACCUM>
__global__ void __launch_bounds__(256, 2)
gemm_k(const float* __restrict__ A, const float* __restrict__ B,
       const float* __restrict__ bias, float* __restrict__ C,
       int M, int K, int Nc) {
    __shared__ float As[16][132];   // transposed A tile, padded
    __shared__ float Bs[16][64];

    const int tid = threadIdx.x;
    const int bm = blockIdx.x * 128;
    const int bn = blockIdx.y * 64;
    const int tr = tid >> 4;            // 0..15
    const int tc = tid & 15;            // 0..15
    const int row0 = tr * 8;
    const int col0 = tc * 4;

    float cacc[8][4];
#pragma unroll
    for (int i = 0; i < 8; i++)
#pragma unroll
        for (int j = 0; j < 4; j++) cacc[i][j] = 0.f;

    const int brow = tid >> 4;          // B tile row 0..15
    const int bcol = (tid & 15) * 4;    // B tile col 0..60
    const bool nvec = ((Nc & 3) == 0);

    for (int k0 = 0; k0 < K; k0 += 16) {
        // --- global loads into registers ---
        float4 av[2];
#pragma unroll
        for (int t = 0; t < 2; t++) {
            int fi = tid + t * 256;       // float4 index in 128x16 tile
            int r = fi >> 2;
            int c4 = (fi & 3) << 2;
            int gr = bm + r, gk = k0 + c4;
            float4 v = make_float4(0.f, 0.f, 0.f, 0.f);
            if (gr < M && gk < K)         // all K are multiples of 4
                v = *(const float4*)(A + (size_t)gr * K + gk);
            av[t] = v;
        }
        float bvv[4] = {0.f, 0.f, 0.f, 0.f};
        {
            int gk = k0 + brow;
            if (gk < K) {
                if (nvec) {
                    int gc = bn + bcol;
                    if (gc < Nc) {
                        float4 v = *(const float4*)(B + (size_t)gk * Nc + gc);
                        bvv[0] = v.x; bvv[1] = v.y; bvv[2] = v.z; bvv[3] = v.w;
                    }
                } else {
#pragma unroll
                    for (int j = 0; j < 4; j++) {
                        int gc = bn + bcol + j;
                        if (gc < Nc) bvv[j] = B[(size_t)gk * Nc + gc];
                    }
                }
            }
        }
        __syncthreads();
#pragma unroll
        for (int t = 0; t < 2; t++) {
            int fi = tid + t * 256;
            int r = fi >> 2;
            int c4 = (fi & 3) << 2;
            As[c4 + 0][r] = av[t].x;
            As[c4 + 1][r] = av[t].y;
            As[c4 + 2][r] = av[t].z;
            As[c4 + 3][r] = av[t].w;
        }
        Bs[brow][bcol + 0] = bvv[0];
        Bs[brow][bcol + 1] = bvv[1];
        Bs[brow][bcol + 2] = bvv[2];
        Bs[brow][bcol + 3] = bvv[3];
        __syncthreads();

#pragma unroll
        for (int kk = 0; kk < 16; kk++) {
            float4 a0 = *(const float4*)&As[kk][row0];
            float4 a1 = *(const float4*)&As[kk][row0 + 4];
            float4 b4 = *(const float4*)&Bs[kk][col0];
            float a[8] = {a0.x, a0.y, a0.z, a0.w, a1.x, a1.y, a1.z, a1.w};
            float b[4] = {b4.x, b4.y, b4.z, b4.w};
#pragma unroll
            for (int i = 0; i < 8; i++)
#pragma unroll
                for (int j = 0; j < 4; j++)
                    cacc[i][j] = fmaf(a[i], b[j], cacc[i][j]);
        }
    }

#pragma unroll
    for (int i = 0; i < 8; i++) {
        int gr = bm + row0 + i;
        if (gr >= M) continue;
#pragma unroll
        for (int j = 0; j < 4; j++) {
            int gc = bn + col0 + j;
            if (gc >= Nc) continue;
            float v = cacc[i][j];
            if (bias) v += bias[gc];
            size_t idx = (size_t)gr * Nc + gc;
            if (ACCUM) C[idx] += v;
            else       C[idx] = v;
        }
    }
}

// ---------------------------------------------------------------
// BatchNorm (training-mode batch stats): stats, finalize, apply
__global__ void bn_zero_k() {
    int t = threadIdx.x;
    g_sum[t] = 0.f;
    g_sq[t] = 0.f;
}

__global__ void bn_stats_k(const float* __restrict__ X, int M) {
    int col = threadIdx.x;   // 256 columns
    int per = (M + gridDim.x - 1) / gridDim.x;
    int r0 = blockIdx.x * per;
    int r1 = min(M, r0 + per);
    float s = 0.f, q = 0.f;
    for (int r = r0; r < r1; r++) {
        float v = X[(size_t)r * Hh + col];
        s += v;
        q = fmaf(v, v, q);
    }
    atomicAdd(&g_sum[col], s);
    atomicAdd(&g_sq[col], q);
}

__global__ void bn_final_k(const float* __restrict__ gamma,
                           const float* __restrict__ beta, float invM) {
    int t = threadIdx.x;
    float mean = g_sum[t] * invM;
    float var = fmaxf(g_sq[t] * invM - mean * mean, 0.f);
    float sc = gamma[t] * rsqrtf(var + 1e-5f);
    g_scale[t] = sc;
    g_shift[t] = beta[t] - mean * sc;
}

// ACT: 0 = ReLU, 1 = LeakyReLU(0.01)
template <int ACT>
__global__ void bn_apply_k(const float* __restrict__ X, float* __restrict__ Y, int n4) {
    int i = blockIdx.x * blockDim.x + threadIdx.x;
    if (i >= n4) return;
    float4 v = ((const float4*)X)[i];
    float4 sc = *(const float4*)&g_scale[(i & 63) << 2];
    float4 sh = *(const float4*)&g_shift[(i & 63) << 2];
    v.x = fmaf(v.x, sc.x, sh.x);
    v.y = fmaf(v.y, sc.y, sh.y);
    v.z = fmaf(v.z, sc.z, sh.z);
    v.w = fmaf(v.w, sc.w, sh.w);
    if (ACT == 0) {
        v.x = fmaxf(v.x, 0.f);
        v.y = fmaxf(v.y, 0.f);
        v.z = fmaxf(v.z, 0.f);
        v.w = fmaxf(v.w, 0.f);
    } else {
        v.x = (v.x > 0.f) ? v.x : 0.01f * v.x;
        v.y = (v.y > 0.f) ? v.y : 0.01f * v.y;
        v.z = (v.z > 0.f) ? v.z : 0.01f * v.z;
        v.w = (v.w > 0.f) ? v.w : 0.01f * v.w;
    }
    ((float4*)Y)[i] = v;
}

// ---------------------------------------------------------------
extern "C" void kernel_launch(void* const* d_in, const int* in_sizes, int n_in,
                              void* d_out, int out_size) {
    (void)in_sizes; (void)n_in; (void)out_size;

    const float* x         = (const float*)d_in[0];
    const int*   esrc      = (const int*)d_in[1];
    const int*   edst      = (const int*)d_in[2];
    const float* W_feat    = (const float*)d_in[3];
    const float* b_feat    = (const float*)d_in[4];
    const float* g_feat    = (const float*)d_in[5];
    const float* beta_feat = (const float*)d_in[6];
    const float* gcn_W     = (const float*)d_in[7];
    const float* gcn_b     = (const float*)d_in[8];
    const float* skip_W    = (const float*)d_in[9];
    const float* skip_b    = (const float*)d_in[10];
    const float* bn_g      = (const float*)d_in[11];
    const float* bn_b      = (const float*)d_in[12];
    const float* W_c1      = (const float*)d_in[13];
    const float* b_c1      = (const float*)d_in[14];
    const float* g_c       = (const float*)d_in[15];
    const float* beta_c    = (const float*)d_in[16];
    const float* W_c2      = (const float*)d_in[17];
    const float* b_c2      = (const float*)d_in[18];
    float* out = (float*)d_out;

    float *hp, *accp, *mp, *coefp, *biasp;
    int *doutp, *dinp;
    cudaGetSymbolAddress((void**)&hp,    g_h);
    cudaGetSymbolAddress((void**)&accp,  g_acc);
    cudaGetSymbolAddress((void**)&mp,    g_m);
    cudaGetSymbolAddress((void**)&coefp, g_coef);
    cudaGetSymbolAddress((void**)&biasp, g_bias);
    cudaGetSymbolAddress((void**)&doutp, g_dout);
    cudaGetSymbolAddress((void**)&dinp,  g_din);

    const int gemm_gx = (Nn + 127) / 128;            // 782
    const dim3 ggridH(gemm_gx, (Hh + 63) / 64);      // Nc = 256 -> y = 4
    const dim3 ggridC(gemm_gx, (Cc + 63) / 64);      // Nc = 23  -> y = 1
    const int apply_n4 = Nn * Hh / 4;
    const int apply_blocks = (apply_n4 + 255) / 256;

    // ---- degrees + per-edge coefficients (input-dependent, deterministic) ----
    zero_k<<<512, 256>>>((float4*)doutp, Rr * Nn / 4);
    zero_k<<<512, 256>>>((float4*)dinp,  Rr * Nn / 4);
    deg_k<<<(Rr * Ee + 255) / 256, 256>>>(esrc, edst, doutp, dinp);
    coef_k<<<(Rr * Ee + 255) / 256, 256>>>(esrc, edst, doutp, dinp, coefp);

    // ---- feat_reduce: Linear + BN + ReLU ----
    gemm_k<false><<<ggridH, 256>>>(x, W_feat, b_feat, accp, Nn, Ff, Hh);
    bn_zero_k<<<1, 256>>>();
    bn_stats_k<<<512, 256>>>(accp, Nn);
    bn_final_k<<<1, 256>>>(g_feat, beta_feat, 1.f / Nn);
    bn_apply_k<0><<<apply_blocks, 256>>>(accp, hp, apply_n4);

    // ---- GCN layers ----
    for (int l = 0; l < Ll; l++) {
        bias_k<<<1, 256>>>(skip_b + (size_t)l * Hh, gcn_b + (size_t)l * Rr * Hh, biasp);
        // acc = h @ skip_W[l] + (skip_b + mean_r gcn_b)
        gemm_k<false><<<ggridH, 256>>>(hp, skip_W + (size_t)l * Hh * Hh, biasp,
                                       accp, Nn, Hh, Hh);
        // m = 0; scatter per-relation normalized messages into [N, 3H]
        zero_k<<<4096, 256>>>((float4*)mp, Nn * 3 * Hh / 4);
        scatter_k<<<(Rr * Ee * 32 + 255) / 256, 256>>>(hp, esrc, edst, coefp, mp);
        // acc += m @ [W_r0; W_r1; W_r2]   (one K=768 GEMM, gcn_W[l] slab is contiguous)
        gemm_k<true><<<ggridH, 256>>>(mp, gcn_W + (size_t)l * Rr * Hh * Hh, nullptr,
                                      accp, Nn, 3 * Hh, Hh);
        // BN + LeakyReLU -> h
        bn_zero_k<<<1, 256>>>();
        bn_stats_k<<<512, 256>>>(accp, Nn);
        bn_final_k<<<1, 256>>>(bn_g + (size_t)l * Hh, bn_b + (size_t)l * Hh, 1.f / Nn);
        bn_apply_k<1><<<apply_blocks, 256>>>(accp, hp, apply_n4);
    }

    // ---- classification head ----
    gemm_k<false><<<ggridH, 256>>>(hp, W_c1, b_c1, accp, Nn, Hh, Hh);
    bn_zero_k<<<1, 256>>>();
    bn_stats_k<<<512, 256>>>(accp, Nn);
    bn_final_k<<<1, 256>>>(g_c, beta_c, 1.f / Nn);
    bn_apply_k<0><<<apply_blocks, 256>>>(accp, hp, apply_n4);

    gemm_k<false><<<ggridC, 256>>>(hp, W_c2, b_c2, out, Nn, Hh, Cc);
}

// round 3
// speedup vs baseline: 2.0442x; 2.0442x over previous
#include <cuda_runtime.h>
#include <cuda_fp16.h>
#include <cstdint>
#include <cstddef>

// Problem constants
constexpr int Nn = 100000;   // nodes
constexpr int Ee = 500000;   // edges per relation
constexpr int Rr = 3;        // relations
constexpr int Ll = 2;        // layers
constexpr int Ff = 300;      // input features
constexpr int Hh = 256;      // hidden
constexpr int Cc = 23;       // classes

// -------- device scratch (static globals: no runtime allocation) --------
__device__ float g_h[(size_t)Nn * Hh];            // current node features (fp32)
__device__ float g_acc[(size_t)Nn * Hh];          // pre-BN accumulator
__device__ float g_m[(size_t)Nn * 3 * Hh];        // scattered messages [N, 3H]
__device__ float g_coef[Rr * Ee];                 // per-edge coefficient
__device__ int   g_dout[Rr * Nn];
__device__ int   g_din[Rr * Nn];
__device__ float g_bias[Hh];                      // combined skip+mean(gcn) bias
__device__ float g_sum[Hh];
__device__ float g_sq[Hh];
__device__ float g_scale[Hh];
__device__ float g_shift[Hh];
__device__ __align__(16) __half g_Bt[256 * 768];  // transposed fp16 weights [N=256, Kpad]

// =====================  misc small kernels  =====================
__global__ void zero_k(float4* __restrict__ p, int n4) {
    int i = blockIdx.x * blockDim.x + threadIdx.x;
    int stride = gridDim.x * blockDim.x;
    float4 z = make_float4(0.f, 0.f, 0.f, 0.f);
    for (; i < n4; i += stride) p[i] = z;
}

__global__ void deg_k(const int* __restrict__ src, const int* __restrict__ dst,
                      int* __restrict__ doutA, int* __restrict__ dinA) {
    int i = blockIdx.x * blockDim.x + threadIdx.x;
    if (i >= Rr * Ee) return;
    int r = i / Ee;
    atomicAdd(&doutA[r * Nn + src[i]], 1);
    atomicAdd(&dinA[r * Nn + dst[i]], 1);
}

__global__ void coef_k(const int* __restrict__ src, const int* __restrict__ dst,
                       const int* __restrict__ doutA, const int* __restrict__ dinA,
                       float* __restrict__ coef) {
    int i = blockIdx.x * blockDim.x + threadIdx.x;
    if (i >= Rr * Ee) return;
    int r = i / Ee;
    float o = (float)max(doutA[r * Nn + src[i]], 1);
    float d = (float)max(dinA[r * Nn + dst[i]], 1);
    coef[i] = rsqrtf(o) * rsqrtf(d) * (1.f / 3.f);
}

// Scatter: one warp per edge; red.global.add.v4.f32
__global__ void scatter_k(const float* __restrict__ h,
                          const int* __restrict__ src, const int* __restrict__ dst,
                          const float* __restrict__ coef, float* __restrict__ m) {
    int gw = (blockIdx.x * blockDim.x + threadIdx.x) >> 5;
    int lane = threadIdx.x & 31;
    if (gw >= Rr * Ee) return;
    int r = gw / Ee;
    int s = __ldg(&src[gw]);
    int d = __ldg(&dst[gw]);
    float c = __ldg(&coef[gw]);
    const float4* hs = (const float4*)(h + (size_t)s * Hh);
    float4* md = (float4*)(m + (size_t)d * (3 * Hh) + r * Hh);
#pragma unroll
    for (int t = 0; t < 2; t++) {
        float4 v = hs[lane + t * 32];
        float4 w = make_float4(v.x * c, v.y * c, v.z * c, v.w * c);
        asm volatile("red.global.add.v4.f32 [%0], {%1,%2,%3,%4};"
                     :: "l"(md + lane + t * 32),
                        "f"(w.x), "f"(w.y), "f"(w.z), "f"(w.w)
                     : "memory");
    }
}

__global__ void bias_k(const float* __restrict__ skip_b,
                       const float* __restrict__ gcn_b,
                       float* __restrict__ bias) {
    int t = threadIdx.x;
    bias[t] = skip_b[t] + (gcn_b[t] + gcn_b[Hh + t] + gcn_b[2 * Hh + t]) * (1.f / 3.f);
}

// Transpose + fp32->fp16 weight prep: Bt[n, k] = W[k, n], zero-padded to Kpad
__global__ void wprep_k(const float* __restrict__ W, __half* __restrict__ Bt,
                        int K, int Kpad) {
    int i = blockIdx.x * blockDim.x + threadIdx.x;
    if (i >= 256 * Kpad) return;
    int n = i / Kpad, k = i % Kpad;
    Bt[i] = (k < K) ? __float2half_rn(W[(size_t)k * 256 + n]) : __float2half_rn(0.f);
}

// =====================  mma.sync fp16 GEMM  =====================
// C[M,256] (+)= A[M,K] @ W[K,256].  A fp32 (converted on SMEM fill),
// B = g_Bt fp16 [256, Kpad] (N-major of K == col-major B: ldmatrix non-trans).
// BM=128, BN=128, BK=64. 8 warps (4x2), warp tile 32x64.
// SMEM: K-major rows of 128 bytes with SW128 swizzle (conflict-free ldmatrix).

__device__ __forceinline__ uint32_t smem_u32(const void* p) {
    uint32_t a;
    asm("{ .reg .u64 t; cvta.to.shared.u64 t, %1; cvt.u32.u64 %0, t; }" : "=r"(a) : "l"(p));
    return a;
}

// byte address of element (row, k[half index]) in a [rows][64] fp16 swizzled tile
__device__ __forceinline__ uint32_t swz(uint32_t base, int row, int k) {
    return base + row * 128 + ((((k >> 3) ^ row) & 7) << 4) + (k & 7) * 2;
}

__device__ __forceinline__ void ldmx4(uint32_t* r, uint32_t addr) {
    asm volatile("ldmatrix.sync.aligned.m8n8.x4.shared.b16 {%0,%1,%2,%3}, [%4];"
                 : "=r"(r[0]), "=r"(r[1]), "=r"(r[2]), "=r"(r[3]) : "r"(addr));
}

__device__ __forceinline__ void mma16816(float* d, const uint32_t* a, const uint32_t* b) {
    asm volatile(
        "mma.sync.aligned.m16n8k16.row.col.f32.f16.f16.f32 "
        "{%0,%1,%2,%3}, {%4,%5,%6,%7}, {%8,%9}, {%0,%1,%2,%3};"
        : "+f"(d[0]), "+f"(d[1]), "+f"(d[2]), "+f"(d[3])
        : "r"(a[0]), "r"(a[1]), "r"(a[2]), "r"(a[3]), "r"(b[0]), "r"(b[1]));
}

template <bool ACCUM>
__global__ void __launch_bounds__(256, 2)
gemm_mma_k(const float* __restrict__ A, const __half* __restrict__ Bt,
           const float* __restrict__ bias, float* __restrict__ C,
           int M, int K, int Kpad) {
    __shared__ __align__(16) char smem[32768];   // As 16KB | Bs 16KB
    const uint32_t SA = smem_u32(smem);
    const uint32_t SB = SA + 16384;

    const int tid = threadIdx.x;
    const int lane = tid & 31;
    const int w = tid >> 5;
    const int wm = (w & 3) * 32;       // warp row base in tile
    const int wn = (w >> 2) * 64;      // warp col base in tile
    const int bm = blockIdx.x * 128;
    const int bn = blockIdx.y * 128;

    float d[2][8][4];
#pragma unroll
    for (int i = 0; i < 2; i++)
#pragma unroll
        for (int j = 0; j < 8; j++)
#pragma unroll
            for (int t = 0; t < 4; t++) d[i][j][t] = 0.f;

    // ldmatrix lane address components (row-of-8x8-tile assignment)
    const int a_r = lane & 15;              // row within 16
    const int a_k = (lane >> 4) * 8;        // 0 or 8
    const int b_r = (lane & 7) + ((lane & 16) ? 8 : 0);
    const int b_k = (lane & 8) ? 8 : 0;

    const int nk = Kpad / 64;
    for (int c = 0; c < nk; c++) {
        const int k0 = c * 64;
        // ---- A tile: 128x64 fp32 -> fp16, swizzled. 4 units of 8 halves per thread
#pragma unroll
        for (int t = 0; t < 4; t++) {
            int u = tid + t * 256;          // 0..1023
            int row = u >> 3, c8 = (u & 7) * 8;
            int gr = bm + row;
            float4 v0 = make_float4(0.f, 0.f, 0.f, 0.f);
            float4 v1 = make_float4(0.f, 0.f, 0.f, 0.f);
            if (gr < M) {
                int gk = k0 + c8;
                if (gk + 7 < K) {
                    v0 = *(const float4*)(A + (size_t)gr * K + gk);
                    v1 = *(const float4*)(A + (size_t)gr * K + gk + 4);
                } else {
                    float tmp[8];
#pragma unroll
                    for (int j = 0; j < 8; j++)
                        tmp[j] = (gk + j < K) ? A[(size_t)gr * K + gk + j] : 0.f;
                    v0 = make_float4(tmp[0], tmp[1], tmp[2], tmp[3]);
                    v1 = make_float4(tmp[4], tmp[5], tmp[6], tmp[7]);
                }
            }
            __half2 h0 = __floats2half2_rn(v0.x, v0.y);
            __half2 h1 = __floats2half2_rn(v0.z, v0.w);
            __half2 h2 = __floats2half2_rn(v1.x, v1.y);
            __half2 h3 = __floats2half2_rn(v1.z, v1.w);
            uint4 o;
            o.x = *(uint32_t*)&h0; o.y = *(uint32_t*)&h1;
            o.z = *(uint32_t*)&h2; o.w = *(uint32_t*)&h3;
            *(uint4*)(uintptr_t)0;  // (no-op to keep formatting honest)
            asm volatile("st.shared.v4.b32 [%0], {%1,%2,%3,%4};"
                         :: "r"(swz(SA, row, c8)), "r"(o.x), "r"(o.y), "r"(o.z), "r"(o.w)
                         : "memory");
        }
        // ---- B tile: 128x64 fp16 from Bt[bn+row][k0+..]
#pragma unroll
        for (int t = 0; t < 4; t++) {
            int u = tid + t * 256;
            int row = u >> 3, c8 = (u & 7) * 8;
            uint4 v = *(const uint4*)(Bt + (size_t)(bn + row) * Kpad + k0 + c8);
            asm volatile("st.shared.v4.b32 [%0], {%1,%2,%3,%4};"
                         :: "r"(swz(SB, row, c8)), "r"(v.x), "r"(v.y), "r"(v.z), "r"(v.w)
                         : "memory");
        }
        __syncthreads();

#pragma unroll
        for (int ks = 0; ks < 64; ks += 16) {
            uint32_t afr[2][4];
#pragma unroll
            for (int mi = 0; mi < 2; mi++)
                ldmx4(afr[mi], swz(SA, wm + mi * 16 + a_r, ks + a_k));
#pragma unroll
            for (int np = 0; np < 4; np++) {
                uint32_t bfr[4];
                ldmx4(bfr, swz(SB, wn + np * 16 + b_r, ks + b_k));
#pragma unroll
                for (int mi = 0; mi < 2; mi++) {
                    mma16816(d[mi][np * 2 + 0], afr[mi], bfr + 0);
                    mma16816(d[mi][np * 2 + 1], afr[mi], bfr + 2);
                }
            }
        }
        __syncthreads();
    }

    // ---- epilogue ----
    const int er = lane >> 2;          // 0..7
    const int ec = (lane & 3) * 2;     // 0,2,4,6
#pragma unroll
    for (int mi = 0; mi < 2; mi++) {
#pragma unroll
        for (int half = 0; half < 2; half++) {
            int gr = bm + wm + mi * 16 + er + half * 8;
            if (gr >= M) continue;
            float* crow = C + (size_t)gr * 256;
#pragma unroll
            for (int ni = 0; ni < 8; ni++) {
                int gc = bn + wn + ni * 8 + ec;
                float v0 = d[mi][ni][half * 2 + 0];
                float v1 = d[mi][ni][half * 2 + 1];
                if (bias) { v0 += bias[gc]; v1 += bias[gc + 1]; }
                if (ACCUM) {
                    float2 o = *(const float2*)(crow + gc);
                    v0 += o.x; v1 += o.y;
                }
                *(float2*)(crow + gc) = make_float2(v0, v1);
            }
        }
    }
}

// =====================  SIMT GEMM (head2 only, N=23)  =====================
template <bool ACCUM>
__global__ void __launch_bounds__(256, 2)
gemm_k(const float* __restrict__ A, const float* __restrict__ B,
       const float* __restrict__ bias, float* __restrict__ C,
       int M, int K, int Nc) {
    __shared__ float As[16][132];
    __shared__ float Bs[16][64];
    const int tid = threadIdx.x;
    const int bm = blockIdx.x * 128;
    const int bn = blockIdx.y * 64;
    const int row0 = (tid >> 4) * 8;
    const int col0 = (tid & 15) * 4;
    float cacc[8][4];
#pragma unroll
    for (int i = 0; i < 8; i++)
#pragma unroll
        for (int j = 0; j < 4; j++) cacc[i][j] = 0.f;
    const int brow = tid >> 4;
    const int bcol = (tid & 15) * 4;
    for (int k0 = 0; k0 < K; k0 += 16) {
        float4 av[2];
#pragma unroll
        for (int t = 0; t < 2; t++) {
            int fi = tid + t * 256;
            int r = fi >> 2, c4 = (fi & 3) << 2;
            int gr = bm + r, gk = k0 + c4;
            float4 v = make_float4(0.f, 0.f, 0.f, 0.f);
            if (gr < M && gk < K) v = *(const float4*)(A + (size_t)gr * K + gk);
            av[t] = v;
        }
        float bvv[4] = {0.f, 0.f, 0.f, 0.f};
        {
            int gk = k0 + brow;
            if (gk < K) {
#pragma unroll
                for (int j = 0; j < 4; j++) {
                    int gc = bn + bcol + j;
                    if (gc < Nc) bvv[j] = B[(size_t)gk * Nc + gc];
                }
            }
        }
        __syncthreads();
#pragma unroll
        for (int t = 0; t < 2; t++) {
            int fi = tid + t * 256;
            int r = fi >> 2, c4 = (fi & 3) << 2;
            As[c4 + 0][r] = av[t].x;
            As[c4 + 1][r] = av[t].y;
            As[c4 + 2][r] = av[t].z;
            As[c4 + 3][r] = av[t].w;
        }
        Bs[brow][bcol + 0] = bvv[0];
        Bs[brow][bcol + 1] = bvv[1];
        Bs[brow][bcol + 2] = bvv[2];
        Bs[brow][bcol + 3] = bvv[3];
        __syncthreads();
#pragma unroll
        for (int kk = 0; kk < 16; kk++) {
            float4 a0 = *(const float4*)&As[kk][row0];
            float4 a1 = *(const float4*)&As[kk][row0 + 4];
            float4 b4 = *(const float4*)&Bs[kk][col0];
            float a[8] = {a0.x, a0.y, a0.z, a0.w, a1.x, a1.y, a1.z, a1.w};
            float b[4] = {b4.x, b4.y, b4.z, b4.w};
#pragma unroll
            for (int i = 0; i < 8; i++)
#pragma unroll
                for (int j = 0; j < 4; j++)
                    cacc[i][j] = fmaf(a[i], b[j], cacc[i][j]);
        }
    }
#pragma unroll
    for (int i = 0; i < 8; i++) {
        int gr = bm + row0 + i;
        if (gr >= M) continue;
#pragma unroll
        for (int j = 0; j < 4; j++) {
            int gc = bn + col0 + j;
            if (gc >= Nc) continue;
            float v = cacc[i][j];
            if (bias) v += bias[gc];
            size_t idx = (size_t)gr * Nc + gc;
            if (ACCUM) C[idx] += v;
            else       C[idx] = v;
        }
    }
}

// =====================  BatchNorm  =====================
__global__ void bn_zero_k() {
    int t = threadIdx.x;
    g_sum[t] = 0.f;
    g_sq[t] = 0.f;
}

__global__ void bn_stats_k(const float* __restrict__ X, int M) {
    int col = threadIdx.x;
    int per = (M + gridDim.x - 1) / gridDim.x;
    int r0 = blockIdx.x * per;
    int r1 = min(M, r0 + per);
    float s = 0.f, q = 0.f;
    for (int r = r0; r < r1; r++) {
        float v = X[(size_t)r * Hh + col];
        s += v;
        q = fmaf(v, v, q);
    }
    atomicAdd(&g_sum[col], s);
    atomicAdd(&g_sq[col], q);
}

__global__ void bn_final_k(const float* __restrict__ gamma,
                           const float* __restrict__ beta, float invM) {
    int t = threadIdx.x;
    float mean = g_sum[t] * invM;
    float var = fmaxf(g_sq[t] * invM - mean * mean, 0.f);
    float sc = gamma[t] * rsqrtf(var + 1e-5f);
    g_scale[t] = sc;
    g_shift[t] = beta[t] - mean * sc;
}

template <int ACT>
__global__ void bn_apply_k(const float* __restrict__ X, float* __restrict__ Y, int n4) {
    int i = blockIdx.x * blockDim.x + threadIdx.x;
    if (i >= n4) return;
    float4 v = ((const float4*)X)[i];
    float4 sc = *(const float4*)&g_scale[(i & 63) << 2];
    float4 sh = *(const float4*)&g_shift[(i & 63) << 2];
    v.x = fmaf(v.x, sc.x, sh.x);
    v.y = fmaf(v.y, sc.y, sh.y);
    v.z = fmaf(v.z, sc.z, sh.z);
    v.w = fmaf(v.w, sc.w, sh.w);
    if (ACT == 0) {
        v.x = fmaxf(v.x, 0.f); v.y = fmaxf(v.y, 0.f);
        v.z = fmaxf(v.z, 0.f); v.w = fmaxf(v.w, 0.f);
    } else {
        v.x = (v.x > 0.f) ? v.x : 0.01f * v.x;
        v.y = (v.y > 0.f) ? v.y : 0.01f * v.y;
        v.z = (v.z > 0.f) ? v.z : 0.01f * v.z;
        v.w = (v.w > 0.f) ? v.w : 0.01f * v.w;
    }
    ((float4*)Y)[i] = v;
}

// =====================  host orchestration  =====================
extern "C" void kernel_launch(void* const* d_in, const int* in_sizes, int n_in,
                              void* d_out, int out_size) {
    (void)in_sizes; (void)n_in; (void)out_size;

    const float* x         = (const float*)d_in[0];
    const int*   esrc      = (const int*)d_in[1];
    const int*   edst      = (const int*)d_in[2];
    const float* W_feat    = (const float*)d_in[3];
    const float* b_feat    = (const float*)d_in[4];
    const float* g_feat    = (const float*)d_in[5];
    const float* beta_feat = (const float*)d_in[6];
    const float* gcn_W     = (const float*)d_in[7];
    const float* gcn_b     = (const float*)d_in[8];
    const float* skip_W    = (const float*)d_in[9];
    const float* skip_b    = (const float*)d_in[10];
    const float* bn_g      = (const float*)d_in[11];
    const float* bn_b      = (const float*)d_in[12];
    const float* W_c1      = (const float*)d_in[13];
    const float* b_c1      = (const float*)d_in[14];
    const float* g_c       = (const float*)d_in[15];
    const float* beta_c    = (const float*)d_in[16];
    const float* W_c2      = (const float*)d_in[17];
    const float* b_c2      = (const float*)d_in[18];
    float* out = (float*)d_out;

    float *hp, *accp, *mp, *coefp, *biasp;
    int *doutp, *dinp;
    __half* btp;
    cudaGetSymbolAddress((void**)&hp,    g_h);
    cudaGetSymbolAddress((void**)&accp,  g_acc);
    cudaGetSymbolAddress((void**)&mp,    g_m);
    cudaGetSymbolAddress((void**)&coefp, g_coef);
    cudaGetSymbolAddress((void**)&biasp, g_bias);
    cudaGetSymbolAddress((void**)&doutp, g_dout);
    cudaGetSymbolAddress((void**)&dinp,  g_din);
    cudaGetSymbolAddress((void**)&btp,   g_Bt);

    const int gx = (Nn + 127) / 128;                 // 782
    const dim3 mgrid(gx, 2);                         // BN=128, N=256
    const int apply_n4 = Nn * Hh / 4;
    const int apply_blocks = (apply_n4 + 255) / 256;
    auto wblocks = [](int Kpad) { return (256 * Kpad + 255) / 256; };

    // ---- degrees + per-edge coefficients ----
    zero_k<<<512, 256>>>((float4*)doutp, Rr * Nn / 4);
    zero_k<<<512, 256>>>((float4*)dinp,  Rr * Nn / 4);
    deg_k<<<(Rr * Ee + 255) / 256, 256>>>(esrc, edst, doutp, dinp);
    coef_k<<<(Rr * Ee + 255) / 256, 256>>>(esrc, edst, doutp, dinp, coefp);

    // ---- feat_reduce: Linear (mma) + BN + ReLU ----
    wprep_k<<<wblocks(320), 256>>>(W_feat, btp, Ff, 320);
    gemm_mma_k<false><<<mgrid, 256>>>(x, btp, b_feat, accp, Nn, Ff, 320);
    bn_zero_k<<<1, 256>>>();
    bn_stats_k<<<512, 256>>>(accp, Nn);
    bn_final_k<<<1, 256>>>(g_feat, beta_feat, 1.f / Nn);
    bn_apply_k<0><<<apply_blocks, 256>>>(accp, hp, apply_n4);

    // ---- GCN layers ----
    for (int l = 0; l < Ll; l++) {
        bias_k<<<1, 256>>>(skip_b + (size_t)l * Hh, gcn_b + (size_t)l * Rr * Hh, biasp);
        // acc = h @ skip_W[l] + (skip_b + mean_r gcn_b)
        wprep_k<<<wblocks(256), 256>>>(skip_W + (size_t)l * Hh * Hh, btp, Hh, 256);
        gemm_mma_k<false><<<mgrid, 256>>>(hp, btp, biasp, accp, Nn, Hh, 256);
        // m = 0; scatter per-relation normalized messages into [N, 3H]
        zero_k<<<4096, 256>>>((float4*)mp, Nn * 3 * Hh / 4);
        scatter_k<<<(Rr * Ee * 32 + 255) / 256, 256>>>(hp, esrc, edst, coefp, mp);
        // acc += m @ [W_r0; W_r1; W_r2]  (one K=768 mma GEMM)
        wprep_k<<<wblocks(768), 256>>>(gcn_W + (size_t)l * Rr * Hh * Hh, btp, 3 * Hh, 768);
        gemm_mma_k<true><<<mgrid, 256>>>(mp, btp, nullptr, accp, Nn, 3 * Hh, 768);
        // BN + LeakyReLU -> h
        bn_zero_k<<<1, 256>>>();
        bn_stats_k<<<512, 256>>>(accp, Nn);
        bn_final_k<<<1, 256>>>(bn_g + (size_t)l * Hh, bn_b + (size_t)l * Hh, 1.f / Nn);
        bn_apply_k<1><<<apply_blocks, 256>>>(accp, hp, apply_n4);
    }

    // ---- classification head ----
    wprep_k<<<wblocks(256), 256>>>(W_c1, btp, Hh, 256);
    gemm_mma_k<false><<<mgrid, 256>>>(hp, btp, b_c1, accp, Nn, Hh, 256);
    bn_zero_k<<<1, 256>>>();
    bn_stats_k<<<512, 256>>>(accp, Nn);
    bn_final_k<<<1, 256>>>(g_c, beta_c, 1.f / Nn);
    bn_apply_k<0><<<apply_blocks, 256>>>(accp, hp, apply_n4);

    gemm_k<false><<<dim3(gx, 1), 256>>>(hp, W_c2, b_c2, out, Nn, Hh, Cc);
}

// round 8
// speedup vs baseline: 2.8964x; 1.4168x over previous
#include <cuda_runtime.h>
#include <cuda_fp16.h>
#include <cstdint>
#include <cstddef>

// Problem constants
constexpr int Nn = 100000;   // nodes
constexpr int Ee = 500000;   // edges per relation
constexpr int Rr = 3;        // relations
constexpr int Ll = 2;        // layers
constexpr int Ff = 300;      // input features
constexpr int Hh = 256;      // hidden
constexpr int Cc = 23;       // classes
constexpr int NSEG = Rr * Nn;    // 300000 CSR segments

// -------- device scratch (static globals: no runtime allocation) --------
__device__ float g_h[(size_t)Nn * Hh];            // current node features (fp32)
__device__ float g_acc[(size_t)Nn * Hh];          // pre-BN accumulator
__device__ float g_m[(size_t)Nn * 3 * Hh];        // gathered messages [N, 3H]
__device__ float g_coef[Rr * Ee];                 // per-edge coefficient
__device__ int   g_dout[Rr * Nn];
__device__ int   g_din[Rr * Nn];
__device__ int   g_off[NSEG + 1];                 // CSR offsets by (r, dst)
__device__ int   g_cursor[NSEG];
__device__ int   g_eids[Rr * Ee];                 // CSR edge ids
__device__ int   g_bsum[512];                     // scan block partials
__device__ float g_bias[Hh];                      // combined skip+mean(gcn) bias
__device__ float g_sum[Hh];
__device__ float g_sq[Hh];
__device__ float g_scale[Hh];
__device__ float g_shift[Hh];
__device__ __align__(16) __half g_Bt[256 * 768];  // transposed fp16 weights [N=256, Kpad]

// =====================  misc small kernels  =====================
__global__ void zero_k(float4* __restrict__ p, int n4) {
    int i = blockIdx.x * blockDim.x + threadIdx.x;
    int stride = gridDim.x * blockDim.x;
    float4 z = make_float4(0.f, 0.f, 0.f, 0.f);
    for (; i < n4; i += stride) p[i] = z;
}

__global__ void deg_k(const int* __restrict__ src, const int* __restrict__ dst,
                      int* __restrict__ doutA, int* __restrict__ dinA) {
    int i = blockIdx.x * blockDim.x + threadIdx.x;
    if (i >= Rr * Ee) return;
    int r = i / Ee;
    atomicAdd(&doutA[r * Nn + src[i]], 1);
    atomicAdd(&dinA[r * Nn + dst[i]], 1);
}

__global__ void coef_k(const int* __restrict__ src, const int* __restrict__ dst,
                       const int* __restrict__ doutA, const int* __restrict__ dinA,
                       float* __restrict__ coef) {
    int i = blockIdx.x * blockDim.x + threadIdx.x;
    if (i >= Rr * Ee) return;
    int r = i / Ee;
    float o = (float)max(doutA[r * Nn + src[i]], 1);
    float d = (float)max(dinA[r * Nn + dst[i]], 1);
    coef[i] = rsqrtf(o) * rsqrtf(d) * (1.f / 3.f);
}

// ---------------- CSR build: 3-kernel exclusive scan + fill ----------------
__global__ void scan1_k(const int* __restrict__ cnt, int* __restrict__ off,
                        int* __restrict__ bsum, int n) {
    __shared__ int wt[32];
    int tid = threadIdx.x, lane = tid & 31, wid = tid >> 5;
    int i = blockIdx.x * 1024 + tid;
    int v = (i < n) ? cnt[i] : 0;
    int x = v;
#pragma unroll
    for (int d = 1; d < 32; d <<= 1) {
        int y = __shfl_up_sync(0xffffffffu, x, d);
        if (lane >= d) x += y;
    }
    if (lane == 31) wt[wid] = x;
    __syncthreads();
    if (wid == 0) {
        int t = wt[lane];
        int tx = t;
#pragma unroll
        for (int d = 1; d < 32; d <<= 1) {
            int y = __shfl_up_sync(0xffffffffu, tx, d);
            if (lane >= d) tx += y;
        }
        wt[lane] = tx - t;   // exclusive
    }
    __syncthreads();
    int excl = wt[wid] + x - v;
    if (i < n) off[i] = excl;
    if (tid == 1023) bsum[blockIdx.x] = excl + v;
}

__global__ void scan2_k(int* __restrict__ bsum, int* __restrict__ off, int nb, int n) {
    __shared__ int wt[32];
    int tid = threadIdx.x, lane = tid & 31, wid = tid >> 5;
    int v = (tid < nb) ? bsum[tid] : 0;
    int x = v;
#pragma unroll
    for (int d = 1; d < 32; d <<= 1) {
        int y = __shfl_up_sync(0xffffffffu, x, d);
        if (lane >= d) x += y;
    }
    if (lane == 31) wt[wid] = x;
    __syncthreads();
    if (wid == 0) {
        int t = wt[lane];
        int tx = t;
#pragma unroll
        for (int d = 1; d < 32; d <<= 1) {
            int y = __shfl_up_sync(0xffffffffu, tx, d);
            if (lane >= d) tx += y;
        }
        wt[lane] = tx - t;
    }
    __syncthreads();
    int excl = wt[wid] + x - v;
    if (tid < nb) bsum[tid] = excl;
    if (tid == nb - 1) off[n] = excl + v;   // grand total
}

__global__ void addback_k(int* __restrict__ off, int* __restrict__ cursor,
                          const int* __restrict__ bsum, int n) {
    int i = blockIdx.x * blockDim.x + threadIdx.x;
    if (i >= n) return;
    int v = off[i] + bsum[i >> 10];
    off[i] = v;
    cursor[i] = v;
}

__global__ void fill_k(const int* __restrict__ dst, int* __restrict__ cursor,
                       int* __restrict__ eids) {
    int i = blockIdx.x * blockDim.x + threadIdx.x;
    if (i >= Rr * Ee) return;
    int r = i / Ee;
    int pos = atomicAdd(&cursor[r * Nn + dst[i]], 1);
    eids[pos] = i;
}

// Gather: one warp per (relation, dst) segment; registers accumulate, single write.
__global__ void gather_k(const float* __restrict__ h, const int* __restrict__ src,
                         const float* __restrict__ coef, const int* __restrict__ eids,
                         const int* __restrict__ off, float* __restrict__ m) {
    int warp = (blockIdx.x * blockDim.x + threadIdx.x) >> 5;
    int lane = threadIdx.x & 31;
    if (warp >= NSEG) return;
    int r = warp / Nn;
    int dstn = warp - r * Nn;
    int e0 = off[warp], e1 = off[warp + 1];
    float4 a0 = make_float4(0.f, 0.f, 0.f, 0.f);
    float4 a1 = make_float4(0.f, 0.f, 0.f, 0.f);
    for (int e = e0; e < e1; e++) {
        int eid = __ldg(&eids[e]);
        int s = __ldg(&src[eid]);
        float c = __ldg(&coef[eid]);
        const float4* hr = (const float4*)(h + (size_t)s * Hh);
        float4 v0 = hr[lane];
        float4 v1 = hr[lane + 32];
        a0.x = fmaf(c, v0.x, a0.x); a0.y = fmaf(c, v0.y, a0.y);
        a0.z = fmaf(c, v0.z, a0.z); a0.w = fmaf(c, v0.w, a0.w);
        a1.x = fmaf(c, v1.x, a1.x); a1.y = fmaf(c, v1.y, a1.y);
        a1.z = fmaf(c, v1.z, a1.z); a1.w = fmaf(c, v1.w, a1.w);
    }
    float4* md = (float4*)(m + (size_t)dstn * (3 * Hh) + r * Hh);
    md[lane] = a0;
    md[lane + 32] = a1;
}

__global__ void bias_k(const float* __restrict__ skip_b,
                       const float* __restrict__ gcn_b,
                       float* __restrict__ bias) {
    int t = threadIdx.x;
    bias[t] = skip_b[t] + (gcn_b[t] + gcn_b[Hh + t] + gcn_b[2 * Hh + t]) * (1.f / 3.f);
}

// Transpose + fp32->fp16 weight prep: Bt[n, k] = W[k, n], zero-padded to Kpad
__global__ void wprep_k(const float* __restrict__ W, __half* __restrict__ Bt,
                        int K, int Kpad) {
    int i = blockIdx.x * blockDim.x + threadIdx.x;
    if (i >= 256 * Kpad) return;
    int n = i / Kpad, k = i % Kpad;
    Bt[i] = (k < K) ? __float2half_rn(W[(size_t)k * 256 + n]) : __float2half_rn(0.f);
}

// =====================  mma.sync fp16 GEMM (pipelined)  =====================
// C[M,256] (+)= A[M,K] @ W[K,256].  A fp32 (converted on SMEM fill),
// B = g_Bt fp16 [256, Kpad] via cp.async.  BM=128, BN=128, BK=64.
// Double-buffered SMEM (64KB dynamic): A 2x16KB | B 2x16KB, SW128 swizzle.

__device__ __forceinline__ uint32_t smem_u32(const void* p) {
    uint32_t a;
    asm("{ .reg .u64 t; cvta.to.shared.u64 t, %1; cvt.u32.u64 %0, t; }" : "=r"(a) : "l"(p));
    return a;
}

// byte address of element (row, k[half index]) in a [128][64] fp16 swizzled tile
__device__ __forceinline__ uint32_t swz(uint32_t base, int row, int k) {
    return base + row * 128 + ((((k >> 3) ^ row) & 7) << 4) + (k & 7) * 2;
}

__device__ __forceinline__ void ldmx4(uint32_t* r, uint32_t addr) {
    asm volatile("ldmatrix.sync.aligned.m8n8.x4.shared.b16 {%0,%1,%2,%3}, [%4];"
                 : "=r"(r[0]), "=r"(r[1]), "=r"(r[2]), "=r"(r[3]) : "r"(addr));
}

__device__ __forceinline__ void mma16816(float* d, const uint32_t* a, const uint32_t* b) {
    asm volatile(
        "mma.sync.aligned.m16n8k16.row.col.f32.f16.f16.f32 "
        "{%0,%1,%2,%3}, {%4,%5,%6,%7}, {%8,%9}, {%0,%1,%2,%3};"
        : "+f"(d[0]), "+f"(d[1]), "+f"(d[2]), "+f"(d[3])
        : "r"(a[0]), "r"(a[1]), "r"(a[2]), "r"(a[3]), "r"(b[0]), "r"(b[1]));
}

constexpr int GEMM_SMEM = 65536;

template <bool ACCUM>
__global__ void __launch_bounds__(256)
gemm_mma_k(const float* __restrict__ A, const __half* __restrict__ Bt,
           const float* __restrict__ bias, float* __restrict__ C,
           int M, int K, int Kpad) {
    extern __shared__ __align__(16) char smem[];
    const uint32_t SA0 = smem_u32(smem);               // 2 x 16KB A stages
    const uint32_t SB0 = SA0 + 32768;                  // 2 x 16KB B stages

    const int tid = threadIdx.x;
    const int lane = tid & 31;
    const int w = tid >> 5;
    const int wm = (w & 3) * 32;       // warp row base in tile
    const int wn = (w >> 2) * 64;      // warp col base in tile
    const int bm = blockIdx.x * 128;
    const int bn = blockIdx.y * 128;

    float d[2][8][4];
#pragma unroll
    for (int i = 0; i < 2; i++)
#pragma unroll
        for (int j = 0; j < 8; j++)
#pragma unroll
            for (int t = 0; t < 4; t++) d[i][j][t] = 0.f;

    // per-thread tile coords for loads (8 halves per unit, 4 units)
    const int arow = tid >> 1;                // used as (u>>3) with u=tid+t*256
    (void)arow;

    // ldmatrix lane address components
    const int a_r = lane & 15;
    const int a_k = (lane >> 4) * 8;
    const int b_r = (lane & 7) + ((lane & 16) ? 8 : 0);
    const int b_k = (lane & 8) ? 8 : 0;

    const int nk = Kpad / 64;

    // ---- helpers ----
    float4 ra[8];   // A chunk prefetch: 4 units x 2 float4

    auto ldgA = [&](int c) {
        const int k0 = c * 64;
#pragma unroll
        for (int t = 0; t < 4; t++) {
            int u = tid + t * 256;
            int row = u >> 3, c8 = (u & 7) * 8;
            int gr = bm + row;
            float4 v0 = make_float4(0.f, 0.f, 0.f, 0.f);
            float4 v1 = make_float4(0.f, 0.f, 0.f, 0.f);
            if (gr < M) {
                int gk = k0 + c8;
                if (gk + 7 < K) {
                    v0 = *(const float4*)(A + (size_t)gr * K + gk);
                    v1 = *(const float4*)(A + (size_t)gr * K + gk + 4);
                } else {
                    float tmp[8];
#pragma unroll
                    for (int j = 0; j < 8; j++)
                        tmp[j] = (gk + j < K) ? A[(size_t)gr * K + gk + j] : 0.f;
                    v0 = make_float4(tmp[0], tmp[1], tmp[2], tmp[3]);
                    v1 = make_float4(tmp[4], tmp[5], tmp[6], tmp[7]);
                }
            }
            ra[t * 2 + 0] = v0;
            ra[t * 2 + 1] = v1;
        }
    };

    auto stsA = [&](int stage) {
        const uint32_t SA = SA0 + stage * 16384;
#pragma unroll
        for (int t = 0; t < 4; t++) {
            int u = tid + t * 256;
            int row = u >> 3, c8 = (u & 7) * 8;
            float4 v0 = ra[t * 2 + 0];
            float4 v1 = ra[t * 2 + 1];
            __half2 h0 = __floats2half2_rn(v0.x, v0.y);
            __half2 h1 = __floats2half2_rn(v0.z, v0.w);
            __half2 h2 = __floats2half2_rn(v1.x, v1.y);
            __half2 h3 = __floats2half2_rn(v1.z, v1.w);
            uint32_t o0 = *(uint32_t*)&h0, o1 = *(uint32_t*)&h1;
            uint32_t o2 = *(uint32_t*)&h2, o3 = *(uint32_t*)&h3;
            asm volatile("st.shared.v4.b32 [%0], {%1,%2,%3,%4};"
                         :: "r"(swz(SA, row, c8)), "r"(o0), "r"(o1), "r"(o2), "r"(o3)
                         : "memory");
        }
    };

    auto cpB = [&](int c, int stage) {
        const int k0 = c * 64;
        const uint32_t SB = SB0 + stage * 16384;
#pragma unroll
        for (int t = 0; t < 4; t++) {
            int u = tid + t * 256;
            int row = u >> 3, c8 = (u & 7) * 8;
            const void* g = Bt + (size_t)(bn + row) * Kpad + k0 + c8;
            asm volatile("cp.async.cg.shared.global [%0], [%1], 16;"
                         :: "r"(swz(SB, row, c8)), "l"(g) : "memory");
        }
        asm volatile("cp.async.commit_group;" ::: "memory");
    };

    // ---- prologue ----
    cpB(0, 0);
    ldgA(0);

    for (int c = 0; c < nk; c++) {
        const int stage = c & 1;
        stsA(stage);
        asm volatile("cp.async.wait_group 0;" ::: "memory");
        __syncthreads();
        if (c + 1 < nk) {
            cpB(c + 1, stage ^ 1);
            ldgA(c + 1);
        }
        const uint32_t SA = SA0 + stage * 16384;
        const uint32_t SB = SB0 + stage * 16384;
#pragma unroll
        for (int ks = 0; ks < 64; ks += 16) {
            uint32_t afr[2][4];
#pragma unroll
            for (int mi = 0; mi < 2; mi++)
                ldmx4(afr[mi], swz(SA, wm + mi * 16 + a_r, ks + a_k));
#pragma unroll
            for (int np = 0; np < 4; np++) {
                uint32_t bfr[4];
                ldmx4(bfr, swz(SB, wn + np * 16 + b_r, ks + b_k));
#pragma unroll
                for (int mi = 0; mi < 2; mi++) {
                    mma16816(d[mi][np * 2 + 0], afr[mi], bfr + 0);
                    mma16816(d[mi][np * 2 + 1], afr[mi], bfr + 2);
                }
            }
        }
        __syncthreads();
    }

    // ---- epilogue ----
    const int er = lane >> 2;
    const int ec = (lane & 3) * 2;
#pragma unroll
    for (int mi = 0; mi < 2; mi++) {
#pragma unroll
        for (int half = 0; half < 2; half++) {
            int gr = bm + wm + mi * 16 + er + half * 8;
            if (gr >= M) continue;
            float* crow = C + (size_t)gr * 256;
#pragma unroll
            for (int ni = 0; ni < 8; ni++) {
                int gc = bn + wn + ni * 8 + ec;
                float v0 = d[mi][ni][half * 2 + 0];
                float v1 = d[mi][ni][half * 2 + 1];
                if (bias) { v0 += bias[gc]; v1 += bias[gc + 1]; }
                if (ACCUM) {
                    float2 o = *(const float2*)(crow + gc);
                    v0 += o.x; v1 += o.y;
                }
                *(float2*)(crow + gc) = make_float2(v0, v1);
            }
        }
    }
}

// =====================  SIMT GEMM (head2 only, N=23)  =====================
template <bool ACCUM>
__global__ void __launch_bounds__(256, 2)
gemm_k(const float* __restrict__ A, const float* __restrict__ B,
       const float* __restrict__ bias, float* __restrict__ C,
       int M, int K, int Nc) {
    __shared__ float As[16][132];
    __shared__ float Bs[16][64];
    const int tid = threadIdx.x;
    const int bm = blockIdx.x * 128;
    const int bn = blockIdx.y * 64;
    const int row0 = (tid >> 4) * 8;
    const int col0 = (tid & 15) * 4;
    float cacc[8][4];
#pragma unroll
    for (int i = 0; i < 8; i++)
#pragma unroll
        for (int j = 0; j < 4; j++) cacc[i][j] = 0.f;
    const int brow = tid >> 4;
    const int bcol = (tid & 15) * 4;
    for (int k0 = 0; k0 < K; k0 += 16) {
        float4 av[2];
#pragma unroll
        for (int t = 0; t < 2; t++) {
            int fi = tid + t * 256;
            int r = fi >> 2, c4 = (fi & 3) << 2;
            int gr = bm + r, gk = k0 + c4;
            float4 v = make_float4(0.f, 0.f, 0.f, 0.f);
            if (gr < M && gk < K) v = *(const float4*)(A + (size_t)gr * K + gk);
            av[t] = v;
        }
        float bvv[4] = {0.f, 0.f, 0.f, 0.f};
        {
            int gk = k0 + brow;
            if (gk < K) {
#pragma unroll
                for (int j = 0; j < 4; j++) {
                    int gc = bn + bcol + j;
                    if (gc < Nc) bvv[j] = B[(size_t)gk * Nc + gc];
                }
            }
        }
        __syncthreads();
#pragma unroll
        for (int t = 0; t < 2; t++) {
            int fi = tid + t * 256;
            int r = fi >> 2, c4 = (fi & 3) << 2;
            As[c4 + 0][r] = av[t].x;
            As[c4 + 1][r] = av[t].y;
            As[c4 + 2][r] = av[t].z;
            As[c4 + 3][r] = av[t].w;
        }
        Bs[brow][bcol + 0] = bvv[0];
        Bs[brow][bcol + 1] = bvv[1];
        Bs[brow][bcol + 2] = bvv[2];
        Bs[brow][bcol + 3] = bvv[3];
        __syncthreads();
#pragma unroll
        for (int kk = 0; kk < 16; kk++) {
            float4 a0 = *(const float4*)&As[kk][row0];
            float4 a1 = *(const float4*)&As[kk][row0 + 4];
            float4 b4 = *(const float4*)&Bs[kk][col0];
            float a[8] = {a0.x, a0.y, a0.z, a0.w, a1.x, a1.y, a1.z, a1.w};
            float b[4] = {b4.x, b4.y, b4.z, b4.w};
#pragma unroll
            for (int i = 0; i < 8; i++)
#pragma unroll
                for (int j = 0; j < 4; j++)
                    cacc[i][j] = fmaf(a[i], b[j], cacc[i][j]);
        }
    }
#pragma unroll
    for (int i = 0; i < 8; i++) {
        int gr = bm + row0 + i;
        if (gr >= M) continue;
#pragma unroll
        for (int j = 0; j < 4; j++) {
            int gc = bn + col0 + j;
            if (gc >= Nc) continue;
            float v = cacc[i][j];
            if (bias) v += bias[gc];
            size_t idx = (size_t)gr * Nc + gc;
            if (ACCUM) C[idx] += v;
            else       C[idx] = v;
        }
    }
}

// =====================  BatchNorm  =====================
__global__ void bn_zero_k() {
    int t = threadIdx.x;
    g_sum[t] = 0.f;
    g_sq[t] = 0.f;
}

__global__ void bn_stats_k(const float* __restrict__ X, int M) {
    int col = threadIdx.x;
    int per = (M + gridDim.x - 1) / gridDim.x;
    int r0 = blockIdx.x * per;
    int r1 = min(M, r0 + per);
    float s = 0.f, q = 0.f;
    for (int r = r0; r < r1; r++) {
        float v = X[(size_t)r * Hh + col];
        s += v;
        q = fmaf(v, v, q);
    }
    atomicAdd(&g_sum[col], s);
    atomicAdd(&g_sq[col], q);
}

__global__ void bn_final_k(const float* __restrict__ gamma,
                           const float* __restrict__ beta, float invM) {
    int t = threadIdx.x;
    float mean = g_sum[t] * invM;
    float var = fmaxf(g_sq[t] * invM - mean * mean, 0.f);
    float sc = gamma[t] * rsqrtf(var + 1e-5f);
    g_scale[t] = sc;
    g_shift[t] = beta[t] - mean * sc;
}

template <int ACT>
__global__ void bn_apply_k(const float* __restrict__ X, float* __restrict__ Y, int n4) {
    int i = blockIdx.x * blockDim.x + threadIdx.x;
    if (i >= n4) return;
    float4 v = ((const float4*)X)[i];
    float4 sc = *(const float4*)&g_scale[(i & 63) << 2];
    float4 sh = *(const float4*)&g_shift[(i & 63) << 2];
    v.x = fmaf(v.x, sc.x, sh.x);
    v.y = fmaf(v.y, sc.y, sh.y);
    v.z = fmaf(v.z, sc.z, sh.z);
    v.w = fmaf(v.w, sc.w, sh.w);
    if (ACT == 0) {
        v.x = fmaxf(v.x, 0.f); v.y = fmaxf(v.y, 0.f);
        v.z = fmaxf(v.z, 0.f); v.w = fmaxf(v.w, 0.f);
    } else {
        v.x = (v.x > 0.f) ? v.x : 0.01f * v.x;
        v.y = (v.y > 0.f) ? v.y : 0.01f * v.y;
        v.z = (v.z > 0.f) ? v.z : 0.01f * v.z;
        v.w = (v.w > 0.f) ? v.w : 0.01f * v.w;
    }
    ((float4*)Y)[i] = v;
}

// =====================  host orchestration  =====================
extern "C" void kernel_launch(void* const* d_in, const int* in_sizes, int n_in,
                              void* d_out, int out_size) {
    (void)in_sizes; (void)n_in; (void)out_size;

    const float* x         = (const float*)d_in[0];
    const int*   esrc      = (const int*)d_in[1];
    const int*   edst      = (const int*)d_in[2];
    const float* W_feat    = (const float*)d_in[3];
    const float* b_feat    = (const float*)d_in[4];
    const float* g_feat    = (const float*)d_in[5];
    const float* beta_feat = (const float*)d_in[6];
    const float* gcn_W     = (const float*)d_in[7];
    const float* gcn_b     = (const float*)d_in[8];
    const float* skip_W    = (const float*)d_in[9];
    const float* skip_b    = (const float*)d_in[10];
    const float* bn_g      = (const float*)d_in[11];
    const float* bn_b      = (const float*)d_in[12];
    const float* W_c1      = (const float*)d_in[13];
    const float* b_c1      = (const float*)d_in[14];
    const float* g_c       = (const float*)d_in[15];
    const float* beta_c    = (const float*)d_in[16];
    const float* W_c2      = (const float*)d_in[17];
    const float* b_c2      = (const float*)d_in[18];
    float* out = (float*)d_out;

    float *hp, *accp, *mp, *coefp, *biasp;
    int *doutp, *dinp, *offp, *curp, *eidsp, *bsump;
    __half* btp;
    cudaGetSymbolAddress((void**)&hp,    g_h);
    cudaGetSymbolAddress((void**)&accp,  g_acc);
    cudaGetSymbolAddress((void**)&mp,    g_m);
    cudaGetSymbolAddress((void**)&coefp, g_coef);
    cudaGetSymbolAddress((void**)&biasp, g_bias);
    cudaGetSymbolAddress((void**)&doutp, g_dout);
    cudaGetSymbolAddress((void**)&dinp,  g_din);
    cudaGetSymbolAddress((void**)&offp,  g_off);
    cudaGetSymbolAddress((void**)&curp,  g_cursor);
    cudaGetSymbolAddress((void**)&eidsp, g_eids);
    cudaGetSymbolAddress((void**)&bsump, g_bsum);
    cudaGetSymbolAddress((void**)&btp,   g_Bt);

    cudaFuncSetAttribute(gemm_mma_k<false>, cudaFuncAttributeMaxDynamicSharedMemorySize, GEMM_SMEM);
    cudaFuncSetAttribute(gemm_mma_k<true>,  cudaFuncAttributeMaxDynamicSharedMemorySize, GEMM_SMEM);

    const int gx = (Nn + 127) / 128;                 // 782
    const dim3 mgrid(gx, 2);                         // BN=128, N=256
    const int apply_n4 = Nn * Hh / 4;
    const int apply_blocks = (apply_n4 + 255) / 256;
    auto wblocks = [](int Kpad) { return (256 * Kpad + 255) / 256; };
    const int eblocks = (Rr * Ee + 255) / 256;
    const int nscan = (NSEG + 1023) / 1024;          // 293

    // ---- degrees + per-edge coefficients ----
    zero_k<<<512, 256>>>((float4*)doutp, Rr * Nn / 4);
    zero_k<<<512, 256>>>((float4*)dinp,  Rr * Nn / 4);
    deg_k<<<eblocks, 256>>>(esrc, edst, doutp, dinp);
    coef_k<<<eblocks, 256>>>(esrc, edst, doutp, dinp, coefp);

    // ---- CSR by (relation, dst): built once, reused by both layers ----
    scan1_k<<<nscan, 1024>>>(dinp, offp, bsump, NSEG);
    scan2_k<<<1, 1024>>>(bsump, offp, nscan, NSEG);
    addback_k<<<(NSEG + 255) / 256, 256>>>(offp, curp, bsump, NSEG);
    fill_k<<<eblocks, 256>>>(edst, curp, eidsp);

    // ---- feat_reduce: Linear (mma) + BN + ReLU ----
    wprep_k<<<wblocks(320), 256>>>(W_feat, btp, Ff, 320);
    gemm_mma_k<false><<<mgrid, 256, GEMM_SMEM>>>(x, btp, b_feat, accp, Nn, Ff, 320);
    bn_zero_k<<<1, 256>>>();
    bn_stats_k<<<512, 256>>>(accp, Nn);
    bn_final_k<<<1, 256>>>(g_feat, beta_feat, 1.f / Nn);
    bn_apply_k<0><<<apply_blocks, 256>>>(accp, hp, apply_n4);

    // ---- GCN layers ----
    for (int l = 0; l < Ll; l++) {
        bias_k<<<1, 256>>>(skip_b + (size_t)l * Hh, gcn_b + (size_t)l * Rr * Hh, biasp);
        // acc = h @ skip_W[l] + (skip_b + mean_r gcn_b)
        wprep_k<<<wblocks(256), 256>>>(skip_W + (size_t)l * Hh * Hh, btp, Hh, 256);
        gemm_mma_k<false><<<mgrid, 256, GEMM_SMEM>>>(hp, btp, biasp, accp, Nn, Hh, 256);
        // m = CSR-gather of normalized messages into [N, 3H] (no zero, no atomics)
        gather_k<<<(NSEG * 32 + 255) / 256, 256>>>(hp, esrc, coefp, eidsp, offp, mp);
        // acc += m @ [W_r0; W_r1; W_r2]  (one K=768 mma GEMM)
        wprep_k<<<wblocks(768), 256>>>(gcn_W + (size_t)l * Rr * Hh * Hh, btp, 3 * Hh, 768);
        gemm_mma_k<true><<<mgrid, 256, GEMM_SMEM>>>(mp, btp, nullptr, accp, Nn, 3 * Hh, 768);
        // BN + LeakyReLU -> h
        bn_zero_k<<<1, 256>>>();
        bn_stats_k<<<512, 256>>>(accp, Nn);
        bn_final_k<<<1, 256>>>(bn_g + (size_t)l * Hh, bn_b + (size_t)l * Hh, 1.f / Nn);
        bn_apply_k<1><<<apply_blocks, 256>>>(accp, hp, apply_n4);
    }

    // ---- classification head ----
    wprep_k<<<wblocks(256), 256>>>(W_c1, btp, Hh, 256);
    gemm_mma_k<false><<<mgrid, 256, GEMM_SMEM>>>(hp, btp, b_c1, accp, Nn, Hh, 256);
    bn_zero_k<<<1, 256>>>();
    bn_stats_k<<<512, 256>>>(accp, Nn);
    bn_final_k<<<1, 256>>>(g_c, beta_c, 1.f / Nn);
    bn_apply_k<0><<<apply_blocks, 256>>>(accp, hp, apply_n4);

    gemm_k<false><<<dim3(gx, 1), 256>>>(hp, W_c2, b_c2, out, Nn, Hh, Cc);
}

// round 9
// speedup vs baseline: 3.4278x; 1.1835x over previous
#include <cuda_runtime.h>
#include <cuda_fp16.h>
#include <cstdint>
#include <cstddef>

// Problem constants
constexpr int Nn = 100000;   // nodes
constexpr int NPAD = 100096; // Nn rounded up to 128 (GEMM tile rows)
constexpr int Ee = 500000;   // edges per relation
constexpr int Rr = 3;        // relations
constexpr int Ll = 2;        // layers
constexpr int Ff = 300;      // input features
constexpr int Hh = 256;      // hidden
constexpr int Cc = 23;       // classes
constexpr int NSEG = Rr * Nn;    // 300000 CSR segments

// -------- device scratch (static globals: no runtime allocation) --------
__device__ float g_h[(size_t)NPAD * Hh];            // node features (fp32, for gather/head2)
__device__ __align__(16) __half g_h16[(size_t)NPAD * Hh];   // fp16 copy (GEMM A)
__device__ __align__(16) __half g_x16[(size_t)NPAD * 320];  // fp16 padded input features
__device__ float g_acc[(size_t)NPAD * Hh];          // pre-BN accumulator
__device__ __align__(16) __half g_m16[(size_t)NPAD * 3 * Hh]; // gathered messages fp16
__device__ float g_coef[Rr * Ee];                   // per-edge coefficient
__device__ int   g_dout[Rr * Nn];
__device__ int   g_din[Rr * Nn];
__device__ int   g_off[NSEG + 1];                   // CSR offsets by (r, dst)
__device__ int   g_cursor[NSEG];
__device__ int   g_csrc[Rr * Ee];                   // CSR-ordered src
__device__ float g_ccoef[Rr * Ee];                  // CSR-ordered coef
__device__ int   g_bsum[512];                       // scan block partials
__device__ float g_bias[Hh];                        // combined skip+mean(gcn) bias
__device__ float g_sum[Hh];
__device__ float g_sq[Hh];
__device__ float g_scale[Hh];
__device__ float g_shift[Hh];
__device__ __align__(16) __half g_Bt[256 * 768];    // transposed fp16 weights [256, Kpad]

// =====================  misc small kernels  =====================
__global__ void zero_k(float4* __restrict__ p, int n4) {
    int i = blockIdx.x * blockDim.x + threadIdx.x;
    int stride = gridDim.x * blockDim.x;
    float4 z = make_float4(0.f, 0.f, 0.f, 0.f);
    for (; i < n4; i += stride) p[i] = z;
}

__global__ void deg_k(const int* __restrict__ src, const int* __restrict__ dst,
                      int* __restrict__ doutA, int* __restrict__ dinA) {
    int i = blockIdx.x * blockDim.x + threadIdx.x;
    if (i >= Rr * Ee) return;
    int r = i / Ee;
    atomicAdd(&doutA[r * Nn + src[i]], 1);
    atomicAdd(&dinA[r * Nn + dst[i]], 1);
}

__global__ void coef_k(const int* __restrict__ src, const int* __restrict__ dst,
                       const int* __restrict__ doutA, const int* __restrict__ dinA,
                       float* __restrict__ coef) {
    int i = blockIdx.x * blockDim.x + threadIdx.x;
    if (i >= Rr * Ee) return;
    int r = i / Ee;
    float o = (float)max(doutA[r * Nn + src[i]], 1);
    float d = (float)max(dinA[r * Nn + dst[i]], 1);
    coef[i] = rsqrtf(o) * rsqrtf(d) * (1.f / 3.f);
}

// ---------------- CSR build: 3-kernel exclusive scan + fill ----------------
__global__ void scan1_k(const int* __restrict__ cnt, int* __restrict__ off,
                        int* __restrict__ bsum, int n) {
    __shared__ int wt[32];
    int tid = threadIdx.x, lane = tid & 31, wid = tid >> 5;
    int i = blockIdx.x * 1024 + tid;
    int v = (i < n) ? cnt[i] : 0;
    int x = v;
#pragma unroll
    for (int d = 1; d < 32; d <<= 1) {
        int y = __shfl_up_sync(0xffffffffu, x, d);
        if (lane >= d) x += y;
    }
    if (lane == 31) wt[wid] = x;
    __syncthreads();
    if (wid == 0) {
        int t = wt[lane];
        int tx = t;
#pragma unroll
        for (int d = 1; d < 32; d <<= 1) {
            int y = __shfl_up_sync(0xffffffffu, tx, d);
            if (lane >= d) tx += y;
        }
        wt[lane] = tx - t;   // exclusive
    }
    __syncthreads();
    int excl = wt[wid] + x - v;
    if (i < n) off[i] = excl;
    if (tid == 1023) bsum[blockIdx.x] = excl + v;
}

__global__ void scan2_k(int* __restrict__ bsum, int* __restrict__ off, int nb, int n) {
    __shared__ int wt[32];
    int tid = threadIdx.x, lane = tid & 31, wid = tid >> 5;
    int v = (tid < nb) ? bsum[tid] : 0;
    int x = v;
#pragma unroll
    for (int d = 1; d < 32; d <<= 1) {
        int y = __shfl_up_sync(0xffffffffu, x, d);
        if (lane >= d) x += y;
    }
    if (lane == 31) wt[wid] = x;
    __syncthreads();
    if (wid == 0) {
        int t = wt[lane];
        int tx = t;
#pragma unroll
        for (int d = 1; d < 32; d <<= 1) {
            int y = __shfl_up_sync(0xffffffffu, tx, d);
            if (lane >= d) tx += y;
        }
        wt[lane] = tx - t;
    }
    __syncthreads();
    int excl = wt[wid] + x - v;
    if (tid < nb) bsum[tid] = excl;
    if (tid == nb - 1) off[n] = excl + v;   // grand total
}

__global__ void addback_k(int* __restrict__ off, int* __restrict__ cursor,
                          const int* __restrict__ bsum, int n) {
    int i = blockIdx.x * blockDim.x + threadIdx.x;
    if (i >= n) return;
    int v = off[i] + bsum[i >> 10];
    off[i] = v;
    cursor[i] = v;
}

__global__ void fill_k(const int* __restrict__ src, const int* __restrict__ dst,
                       const float* __restrict__ coef, int* __restrict__ cursor,
                       int* __restrict__ csrc, float* __restrict__ ccoef) {
    int i = blockIdx.x * blockDim.x + threadIdx.x;
    if (i >= Rr * Ee) return;
    int r = i / Ee;
    int pos = atomicAdd(&cursor[r * Nn + dst[i]], 1);
    csrc[pos] = src[i];
    ccoef[pos] = coef[i];
}

// Gather: one warp per (relation, dst) segment; fp32 accumulate, fp16 write.
__global__ void gather_k(const float* __restrict__ h, const int* __restrict__ csrc,
                         const float* __restrict__ ccoef, const int* __restrict__ off,
                         __half* __restrict__ m16) {
    int warp = (blockIdx.x * blockDim.x + threadIdx.x) >> 5;
    int lane = threadIdx.x & 31;
    if (warp >= NSEG) return;
    int r = warp / Nn;
    int dstn = warp - r * Nn;
    int e0 = off[warp], e1 = off[warp + 1];
    float4 a0 = make_float4(0.f, 0.f, 0.f, 0.f);
    float4 a1 = make_float4(0.f, 0.f, 0.f, 0.f);
    for (int e = e0; e < e1; e++) {
        int s = __ldg(&csrc[e]);
        float c = __ldg(&ccoef[e]);
        const float4* hr = (const float4*)(h + (size_t)s * Hh);
        float4 v0 = hr[lane];
        float4 v1 = hr[lane + 32];
        a0.x = fmaf(c, v0.x, a0.x); a0.y = fmaf(c, v0.y, a0.y);
        a0.z = fmaf(c, v0.z, a0.z); a0.w = fmaf(c, v0.w, a0.w);
        a1.x = fmaf(c, v1.x, a1.x); a1.y = fmaf(c, v1.y, a1.y);
        a1.z = fmaf(c, v1.z, a1.z); a1.w = fmaf(c, v1.w, a1.w);
    }
    __half* md = m16 + (size_t)dstn * (3 * Hh) + r * Hh;
    __half2 p0 = __floats2half2_rn(a0.x, a0.y);
    __half2 p1 = __floats2half2_rn(a0.z, a0.w);
    __half2 p2 = __floats2half2_rn(a1.x, a1.y);
    __half2 p3 = __floats2half2_rn(a1.z, a1.w);
    uint2 u0 = make_uint2(*(uint32_t*)&p0, *(uint32_t*)&p1);
    uint2 u1 = make_uint2(*(uint32_t*)&p2, *(uint32_t*)&p3);
    *(uint2*)(md + lane * 4) = u0;
    *(uint2*)(md + 128 + lane * 4) = u1;
}

__global__ void bias_k(const float* __restrict__ skip_b,
                       const float* __restrict__ gcn_b,
                       float* __restrict__ bias) {
    int t = threadIdx.x;
    bias[t] = skip_b[t] + (gcn_b[t] + gcn_b[Hh + t] + gcn_b[2 * Hh + t]) * (1.f / 3.f);
}

// Transpose + fp32->fp16 weight prep: Bt[n, k] = W[k, n], zero-padded to Kpad
__global__ void wprep_k(const float* __restrict__ W, __half* __restrict__ Bt,
                        int K, int Kpad) {
    int i = blockIdx.x * blockDim.x + threadIdx.x;
    if (i >= 256 * Kpad) return;
    int n = i / Kpad, k = i % Kpad;
    Bt[i] = (k < K) ? __float2half_rn(W[(size_t)k * 256 + n]) : __float2half_rn(0.f);
}

// x fp32 [Nn,300] -> fp16 [NPAD,320] zero-padded columns
__global__ void xconv_k(const float* __restrict__ x, __half* __restrict__ x16) {
    int i = blockIdx.x * blockDim.x + threadIdx.x;
    if (i >= Nn * 320) return;
    int row = i / 320, k = i - row * 320;
    x16[i] = (k < Ff) ? __float2half_rn(x[(size_t)row * Ff + k]) : __float2half_rn(0.f);
}

// =====================  mma.sync fp16 GEMM (pipelined, fp16 A, fused BN stats)  ===========
// C[M,256] (+)= A16[M,Kpad] @ Bt^T.  Both operands cp.async fp16.
// BM=128, BN=128, BK=64, double-buffered (64KB dynamic), SW128 swizzle.
// STATS: epilogue accumulates per-column sum/sumsq into g_sum/g_sq (pre-zeroed).

__device__ __forceinline__ uint32_t smem_u32(const void* p) {
    uint32_t a;
    asm("{ .reg .u64 t; cvta.to.shared.u64 t, %1; cvt.u32.u64 %0, t; }" : "=r"(a) : "l"(p));
    return a;
}

__device__ __forceinline__ uint32_t swz(uint32_t base, int row, int k) {
    return base + row * 128 + ((((k >> 3) ^ row) & 7) << 4) + (k & 7) * 2;
}

__device__ __forceinline__ void ldmx4(uint32_t* r, uint32_t addr) {
    asm volatile("ldmatrix.sync.aligned.m8n8.x4.shared.b16 {%0,%1,%2,%3}, [%4];"
                 : "=r"(r[0]), "=r"(r[1]), "=r"(r[2]), "=r"(r[3]) : "r"(addr));
}

__device__ __forceinline__ void mma16816(float* d, const uint32_t* a, const uint32_t* b) {
    asm volatile(
        "mma.sync.aligned.m16n8k16.row.col.f32.f16.f16.f32 "
        "{%0,%1,%2,%3}, {%4,%5,%6,%7}, {%8,%9}, {%0,%1,%2,%3};"
        : "+f"(d[0]), "+f"(d[1]), "+f"(d[2]), "+f"(d[3])
        : "r"(a[0]), "r"(a[1]), "r"(a[2]), "r"(a[3]), "r"(b[0]), "r"(b[1]));
}

constexpr int GEMM_SMEM = 65536;

template <bool ACCUM, bool STATS>
__global__ void __launch_bounds__(256)
gemm_mma_k(const __half* __restrict__ A, const __half* __restrict__ Bt,
           const float* __restrict__ bias, float* __restrict__ C,
           int M, int Kpad) {
    extern __shared__ __align__(16) char smem[];
    const uint32_t SA0 = smem_u32(smem);               // 2 x 16KB A stages
    const uint32_t SB0 = SA0 + 32768;                  // 2 x 16KB B stages

    const int tid = threadIdx.x;
    const int lane = tid & 31;
    const int w = tid >> 5;
    const int wm = (w & 3) * 32;
    const int wn = (w >> 2) * 64;
    const int bm = blockIdx.x * 128;
    const int bn = blockIdx.y * 128;

    float d[2][8][4];
#pragma unroll
    for (int i = 0; i < 2; i++)
#pragma unroll
        for (int j = 0; j < 8; j++)
#pragma unroll
            for (int t = 0; t < 4; t++) d[i][j][t] = 0.f;

    const int a_r = lane & 15;
    const int a_k = (lane >> 4) * 8;
    const int b_r = (lane & 7) + ((lane & 16) ? 8 : 0);
    const int b_k = (lane & 8) ? 8 : 0;

    const int nk = Kpad / 64;

    auto cpAB = [&](int c, int stage) {
        const int k0 = c * 64;
        const uint32_t SA = SA0 + stage * 16384;
        const uint32_t SB = SB0 + stage * 16384;
#pragma unroll
        for (int t = 0; t < 4; t++) {
            int u = tid + t * 256;
            int row = u >> 3, c8 = (u & 7) * 8;
            const void* ga = A + (size_t)(bm + row) * Kpad + k0 + c8;
            asm volatile("cp.async.cg.shared.global [%0], [%1], 16;"
                         :: "r"(swz(SA, row, c8)), "l"(ga) : "memory");
            const void* gb = Bt + (size_t)(bn + row) * Kpad + k0 + c8;
            asm volatile("cp.async.cg.shared.global [%0], [%1], 16;"
                         :: "r"(swz(SB, row, c8)), "l"(gb) : "memory");
        }
        asm volatile("cp.async.commit_group;" ::: "memory");
    };

    cpAB(0, 0);

    for (int c = 0; c < nk; c++) {
        const int stage = c & 1;
        if (c + 1 < nk) cpAB(c + 1, stage ^ 1);
        if (c + 1 < nk)
            asm volatile("cp.async.wait_group 1;" ::: "memory");
        else
            asm volatile("cp.async.wait_group 0;" ::: "memory");
        __syncthreads();
        const uint32_t SA = SA0 + stage * 16384;
        const uint32_t SB = SB0 + stage * 16384;
#pragma unroll
        for (int ks = 0; ks < 64; ks += 16) {
            uint32_t afr[2][4];
#pragma unroll
            for (int mi = 0; mi < 2; mi++)
                ldmx4(afr[mi], swz(SA, wm + mi * 16 + a_r, ks + a_k));
#pragma unroll
            for (int np = 0; np < 4; np++) {
                uint32_t bfr[4];
                ldmx4(bfr, swz(SB, wn + np * 16 + b_r, ks + b_k));
#pragma unroll
                for (int mi = 0; mi < 2; mi++) {
                    mma16816(d[mi][np * 2 + 0], afr[mi], bfr + 0);
                    mma16816(d[mi][np * 2 + 1], afr[mi], bfr + 2);
                }
            }
        }
        __syncthreads();
    }

    // ---- epilogue (+ optional fused BN stats) ----
    const int er = lane >> 2;
    const int ec = (lane & 3) * 2;
#pragma unroll
    for (int mi = 0; mi < 2; mi++) {
#pragma unroll
        for (int half = 0; half < 2; half++) {
            int gr = bm + wm + mi * 16 + er + half * 8;
            bool ok = gr < M;
            float* crow = C + (size_t)gr * 256;
#pragma unroll
            for (int ni = 0; ni < 8; ni++) {
                int gc = bn + wn + ni * 8 + ec;
                float v0 = d[mi][ni][half * 2 + 0];
                float v1 = d[mi][ni][half * 2 + 1];
                if (bias) { v0 += bias[gc]; v1 += bias[gc + 1]; }
                if (ok) {
                    if (ACCUM) {
                        float2 o = *(const float2*)(crow + gc);
                        v0 += o.x; v1 += o.y;
                    }
                    *(float2*)(crow + gc) = make_float2(v0, v1);
                } else {
                    v0 = 0.f; v1 = 0.f;
                }
                if (STATS) {
                    d[mi][ni][half * 2 + 0] = v0;
                    d[mi][ni][half * 2 + 1] = v1;
                }
            }
        }
    }
    if (STATS) {
#pragma unroll
        for (int ni = 0; ni < 8; ni++) {
            float s0 = 0.f, q0 = 0.f, s1 = 0.f, q1 = 0.f;
#pragma unroll
            for (int mi = 0; mi < 2; mi++)
#pragma unroll
                for (int half = 0; half < 2; half++) {
                    float v0 = d[mi][ni][half * 2 + 0];
                    float v1 = d[mi][ni][half * 2 + 1];
                    s0 += v0; q0 = fmaf(v0, v0, q0);
                    s1 += v1; q1 = fmaf(v1, v1, q1);
                }
#pragma unroll
            for (int o = 4; o <= 16; o <<= 1) {
                s0 += __shfl_xor_sync(0xffffffffu, s0, o);
                q0 += __shfl_xor_sync(0xffffffffu, q0, o);
                s1 += __shfl_xor_sync(0xffffffffu, s1, o);
                q1 += __shfl_xor_sync(0xffffffffu, q1, o);
            }
            if (lane < 4) {
                int gc = bn + wn + ni * 8 + ec;
                atomicAdd(&g_sum[gc], s0);
                atomicAdd(&g_sq[gc], q0);
                atomicAdd(&g_sum[gc + 1], s1);
                atomicAdd(&g_sq[gc + 1], q1);
            }
        }
    }
}

// =====================  head2: out[M,23] = h[M,256] @ W[256,23] + b  =====================
// Thread-per-row; h staged through smem transposed (conflict-free), W in smem.
constexpr int H2_SMEM = 64 * 257 * 4 + 256 * 24 * 4;   // 65792 + 24576 = 90368

__global__ void __launch_bounds__(256)
head2_k(const float* __restrict__ h, const float* __restrict__ W,
        const float* __restrict__ b, float* __restrict__ out, int M) {
    extern __shared__ float sm[];
    float* tile = sm;              // [64][257] transposed chunk
    float* Bs = sm + 64 * 257;     // [256][24]
    const int tid = threadIdx.x;
    const int r0 = blockIdx.x * 256;

    for (int i = tid; i < 256 * 24; i += 256) {
        int k = i / 24, c = i - k * 24;
        Bs[i] = (c < Cc) ? W[k * Cc + c] : 0.f;
    }

    float acc[24];
#pragma unroll
    for (int c = 0; c < 24; c++) acc[c] = 0.f;

    for (int k0 = 0; k0 < 256; k0 += 64) {
        __syncthreads();
        for (int f = tid; f < 4096; f += 256) {     // 256 rows x 16 float4
            int row = f >> 4, c4 = (f & 15) << 2;
            int gr = r0 + row;
            float4 v = make_float4(0.f, 0.f, 0.f, 0.f);
            if (gr < M) v = *(const float4*)(h + (size_t)gr * 256 + k0 + c4);
            tile[(c4 + 0) * 257 + row] = v.x;
            tile[(c4 + 1) * 257 + row] = v.y;
            tile[(c4 + 2) * 257 + row] = v.z;
            tile[(c4 + 3) * 257 + row] = v.w;
        }
        __syncthreads();
#pragma unroll 4
        for (int k = 0; k < 64; k++) {
            float a = tile[k * 257 + tid];
            const float* br = Bs + (k0 + k) * 24;
#pragma unroll
            for (int c = 0; c < 24; c += 4) {
                float4 bv = *(const float4*)(br + c);
                acc[c + 0] = fmaf(a, bv.x, acc[c + 0]);
                acc[c + 1] = fmaf(a, bv.y, acc[c + 1]);
                acc[c + 2] = fmaf(a, bv.z, acc[c + 2]);
                acc[c + 3] = fmaf(a, bv.w, acc[c + 3]);
            }
        }
    }

    int gr = r0 + tid;
    if (gr < M) {
        float* orow = out + (size_t)gr * Cc;
#pragma unroll
        for (int c = 0; c < Cc; c++) orow[c] = acc[c] + b[c];
    }
}

// =====================  BatchNorm  =====================
__global__ void bn_zero_k() {
    int t = threadIdx.x;
    g_sum[t] = 0.f;
    g_sq[t] = 0.f;
}

__global__ void bn_final_k(const float* __restrict__ gamma,
                           const float* __restrict__ beta, float invM) {
    int t = threadIdx.x;
    float mean = g_sum[t] * invM;
    float var = fmaxf(g_sq[t] * invM - mean * mean, 0.f);
    float sc = gamma[t] * rsqrtf(var + 1e-5f);
    g_scale[t] = sc;
    g_shift[t] = beta[t] - mean * sc;
}

// ACT 0 = ReLU, 1 = LeakyReLU(0.01). Writes fp32 Y and fp16 Y16.
template <int ACT>
__global__ void bn_apply_k(const float* __restrict__ X, float* __restrict__ Y,
                           __half* __restrict__ Y16, int n4) {
    int i = blockIdx.x * blockDim.x + threadIdx.x;
    if (i >= n4) return;
    float4 v = ((const float4*)X)[i];
    float4 sc = *(const float4*)&g_scale[(i & 63) << 2];
    float4 sh = *(const float4*)&g_shift[(i & 63) << 2];
    v.x = fmaf(v.x, sc.x, sh.x);
    v.y = fmaf(v.y, sc.y, sh.y);
    v.z = fmaf(v.z, sc.z, sh.z);
    v.w = fmaf(v.w, sc.w, sh.w);
    if (ACT == 0) {
        v.x = fmaxf(v.x, 0.f); v.y = fmaxf(v.y, 0.f);
        v.z = fmaxf(v.z, 0.f); v.w = fmaxf(v.w, 0.f);
    } else {
        v.x = (v.x > 0.f) ? v.x : 0.01f * v.x;
        v.y = (v.y > 0.f) ? v.y : 0.01f * v.y;
        v.z = (v.z > 0.f) ? v.z : 0.01f * v.z;
        v.w = (v.w > 0.f) ? v.w : 0.01f * v.w;
    }
    ((float4*)Y)[i] = v;
    __half2 p0 = __floats2half2_rn(v.x, v.y);
    __half2 p1 = __floats2half2_rn(v.z, v.w);
    ((uint2*)Y16)[i] = make_uint2(*(uint32_t*)&p0, *(uint32_t*)&p1);
}

// =====================  host orchestration  =====================
extern "C" void kernel_launch(void* const* d_in, const int* in_sizes, int n_in,
                              void* d_out, int out_size) {
    (void)in_sizes; (void)n_in; (void)out_size;

    const float* x         = (const float*)d_in[0];
    const int*   esrc      = (const int*)d_in[1];
    const int*   edst      = (const int*)d_in[2];
    const float* W_feat    = (const float*)d_in[3];
    const float* b_feat    = (const float*)d_in[4];
    const float* g_feat    = (const float*)d_in[5];
    const float* beta_feat = (const float*)d_in[6];
    const float* gcn_W     = (const float*)d_in[7];
    const float* gcn_b     = (const float*)d_in[8];
    const float* skip_W    = (const float*)d_in[9];
    const float* skip_b    = (const float*)d_in[10];
    const float* bn_g      = (const float*)d_in[11];
    const float* bn_b      = (const float*)d_in[12];
    const float* W_c1      = (const float*)d_in[13];
    const float* b_c1      = (const float*)d_in[14];
    const float* g_c       = (const float*)d_in[15];
    const float* beta_c    = (const float*)d_in[16];
    const float* W_c2      = (const float*)d_in[17];
    const float* b_c2      = (const float*)d_in[18];
    float* out = (float*)d_out;

    float *hp, *accp, *coefp, *biasp, *ccoefp;
    int *doutp, *dinp, *offp, *curp, *csrcp, *bsump;
    __half *btp, *h16p, *x16p, *m16p;
    cudaGetSymbolAddress((void**)&hp,     g_h);
    cudaGetSymbolAddress((void**)&h16p,   g_h16);
    cudaGetSymbolAddress((void**)&x16p,   g_x16);
    cudaGetSymbolAddress((void**)&accp,   g_acc);
    cudaGetSymbolAddress((void**)&m16p,   g_m16);
    cudaGetSymbolAddress((void**)&coefp,  g_coef);
    cudaGetSymbolAddress((void**)&biasp,  g_bias);
    cudaGetSymbolAddress((void**)&doutp,  g_dout);
    cudaGetSymbolAddress((void**)&dinp,   g_din);
    cudaGetSymbolAddress((void**)&offp,   g_off);
    cudaGetSymbolAddress((void**)&curp,   g_cursor);
    cudaGetSymbolAddress((void**)&csrcp,  g_csrc);
    cudaGetSymbolAddress((void**)&ccoefp, g_ccoef);
    cudaGetSymbolAddress((void**)&bsump,  g_bsum);
    cudaGetSymbolAddress((void**)&btp,    g_Bt);

    cudaFuncSetAttribute(gemm_mma_k<false, false>, cudaFuncAttributeMaxDynamicSharedMemorySize, GEMM_SMEM);
    cudaFuncSetAttribute(gemm_mma_k<false, true>,  cudaFuncAttributeMaxDynamicSharedMemorySize, GEMM_SMEM);
    cudaFuncSetAttribute(gemm_mma_k<true,  true>,  cudaFuncAttributeMaxDynamicSharedMemorySize, GEMM_SMEM);
    cudaFuncSetAttribute(head2_k, cudaFuncAttributeMaxDynamicSharedMemorySize, H2_SMEM);

    const int gx = (Nn + 127) / 128;                 // 782
    const dim3 mgrid(gx, 2);
    const int apply_n4 = Nn * Hh / 4;
    const int apply_blocks = (apply_n4 + 255) / 256;
    auto wblocks = [](int Kpad) { return (256 * Kpad + 255) / 256; };
    const int eblocks = (Rr * Ee + 255) / 256;
    const int nscan = (NSEG + 1023) / 1024;          // 293

    // ---- degrees + per-edge coefficients ----
    zero_k<<<512, 256>>>((float4*)doutp, Rr * Nn / 4);
    zero_k<<<512, 256>>>((float4*)dinp,  Rr * Nn / 4);
    deg_k<<<eblocks, 256>>>(esrc, edst, doutp, dinp);
    coef_k<<<eblocks, 256>>>(esrc, edst, doutp, dinp, coefp);

    // ---- CSR by (relation, dst) with inlined (src, coef) payload ----
    scan1_k<<<nscan, 1024>>>(dinp, offp, bsump, NSEG);
    scan2_k<<<1, 1024>>>(bsump, offp, nscan, NSEG);
    addback_k<<<(NSEG + 255) / 256, 256>>>(offp, curp, bsump, NSEG);
    fill_k<<<eblocks, 256>>>(esrc, edst, coefp, curp, csrcp, ccoefp);

    // ---- feat_reduce: x->fp16, Linear (mma, fused stats) + BN + ReLU ----
    xconv_k<<<(Nn * 320 + 255) / 256, 256>>>(x, x16p);
    wprep_k<<<wblocks(320), 256>>>(W_feat, btp, Ff, 320);
    bn_zero_k<<<1, 256>>>();
    gemm_mma_k<false, true><<<mgrid, 256, GEMM_SMEM>>>(x16p, btp, b_feat, accp, Nn, 320);
    bn_final_k<<<1, 256>>>(g_feat, beta_feat, 1.f / Nn);
    bn_apply_k<0><<<apply_blocks, 256>>>(accp, hp, h16p, apply_n4);

    // ---- GCN layers ----
    for (int l = 0; l < Ll; l++) {
        bias_k<<<1, 256>>>(skip_b + (size_t)l * Hh, gcn_b + (size_t)l * Rr * Hh, biasp);
        wprep_k<<<wblocks(256), 256>>>(skip_W + (size_t)l * Hh * Hh, btp, Hh, 256);
        gemm_mma_k<false, false><<<mgrid, 256, GEMM_SMEM>>>(h16p, btp, biasp, accp, Nn, 256);
        // m16 = CSR-gather of normalized messages (fp32 accumulate, fp16 store)
        gather_k<<<(NSEG * 32 + 255) / 256, 256>>>(hp, csrcp, ccoefp, offp, m16p);
        // acc += m @ [W_r0; W_r1; W_r2], fused BN stats
        wprep_k<<<wblocks(768), 256>>>(gcn_W + (size_t)l * Rr * Hh * Hh, btp, 3 * Hh, 768);
        bn_zero_k<<<1, 256>>>();
        gemm_mma_k<true, true><<<mgrid, 256, GEMM_SMEM>>>(m16p, btp, nullptr, accp, Nn, 768);
        bn_final_k<<<1, 256>>>(bn_g + (size_t)l * Hh, bn_b + (size_t)l * Hh, 1.f / Nn);
        bn_apply_k<1><<<apply_blocks, 256>>>(accp, hp, h16p, apply_n4);
    }

    // ---- classification head ----
    wprep_k<<<wblocks(256), 256>>>(W_c1, btp, Hh, 256);
    bn_zero_k<<<1, 256>>>();
    gemm_mma_k<false, true><<<mgrid, 256, GEMM_SMEM>>>(h16p, btp, b_c1, accp, Nn, 256);
    bn_final_k<<<1, 256>>>(g_c, beta_c, 1.f / Nn);
    bn_apply_k<0><<<apply_blocks, 256>>>(accp, hp, h16p, apply_n4);

    head2_k<<<(Nn + 255) / 256, 256, H2_SMEM>>>(hp, W_c2, b_c2, out, Nn);
}